// round 7
// baseline (speedup 1.0000x reference)
#include <cuda_runtime.h>

#define LSEQ 2048
#define NH 8
#define DKH 128
#define DVH 128
#define CIN 3072
#define CH 32
#define NCH (LSEQ/CH)        // 64
#define CHH (NCH*NH)         // 512 chunk-heads

// ------------------------- global scratch (static) -------------------------
__device__ float  g_q [LSEQ*NH*DKH];
__device__ float  g_k [LSEQ*NH*DKH];
__device__ float  g_v [LSEQ*NH*DVH];
__device__ float2 g_gb[LSEQ*NH];          // (g, beta) raw
__device__ float4 g_sc[CHH*CH];           // (E_t, beta_t, exp(cg31-cg_t), cg_t)
__device__ float  g_gamma[CHH];           // E_31 per chunk-head
__device__ float  g_A[CHH*CH*CH];         // strictly-lower A
__device__ float  g_M[CHH*CH*36];         // lower-incl M (padded rows, 36)
__device__ float  g_T[CHH*CH*36];         // (I+A)^-1   (padded rows, 36)

// ------------------------- cp.async helpers -------------------------
__device__ __forceinline__ unsigned smem_u32(const void* p) {
    return (unsigned)__cvta_generic_to_shared(p);
}
__device__ __forceinline__ void cp16(void* dst, const void* src) {
    asm volatile("cp.async.cg.shared.global [%0], [%1], 16;" :: "r"(smem_u32(dst)), "l"(src));
}
__device__ __forceinline__ void cp_commit() { asm volatile("cp.async.commit_group;"); }
template<int N> __device__ __forceinline__ void cp_wait() {
    asm volatile("cp.async.wait_group %0;" :: "n"(N));
}

// ---------------------------------------------------------------------------
// K1: conv(K=4)+SiLU+split+l2norm. 4 timesteps per block. grid (512,24), blk 128.
// ---------------------------------------------------------------------------
__global__ void prep_kernel(const float* __restrict__ x,
                            const float* __restrict__ w,
                            const float* __restrict__ bias) {
    const int t0 = blockIdx.x * 4;
    const int g = blockIdx.y, d = threadIdx.x;
    const int c = g*128 + d;
    const float4 wv = ((const float4*)w)[c];
    const float bi = bias[c];

    float xw[7];
    #pragma unroll
    for (int i = 0; i < 7; i++) {
        int t = t0 - 3 + i;
        xw[i] = (t >= 0) ? x[t*CIN + c] : 0.f;
    }
    float val[4];
    #pragma unroll
    for (int i = 0; i < 4; i++) {
        float acc = bi;
        acc = fmaf(xw[i  ], wv.x, acc);
        acc = fmaf(xw[i+1], wv.y, acc);
        acc = fmaf(xw[i+2], wv.z, acc);
        acc = fmaf(xw[i+3], wv.w, acc);
        val[i] = acc / (1.f + __expf(-acc));
    }

    __shared__ float red[4][4];
    if (g < 16) {
        float sq[4];
        #pragma unroll
        for (int i = 0; i < 4; i++) sq[i] = val[i]*val[i];
        #pragma unroll
        for (int off = 16; off; off >>= 1) {
            #pragma unroll
            for (int i = 0; i < 4; i++) sq[i] += __shfl_xor_sync(0xffffffffu, sq[i], off);
        }
        if ((d & 31) == 0) {
            #pragma unroll
            for (int i = 0; i < 4; i++) red[i][d >> 5] = sq[i];
        }
        __syncthreads();
        #pragma unroll
        for (int i = 0; i < 4; i++)
            val[i] *= rsqrtf(red[i][0]+red[i][1]+red[i][2]+red[i][3] + 1e-6f);
    }
    #pragma unroll
    for (int i = 0; i < 4; i++) {
        int t = t0 + i;
        if (g < 8)       g_q[(t*NH + g)*DKH + d]      = val[i] * 0.08838834764831845f;
        else if (g < 16) g_k[(t*NH + (g-8))*DKH + d]  = val[i];
        else             g_v[(t*NH + (g-16))*DVH + d] = val[i];
    }
}

// ---------------------------------------------------------------------------
// K2: gating
// ---------------------------------------------------------------------------
__global__ void gate_kernel(const float* __restrict__ a,
                            const float* __restrict__ b,
                            const float* __restrict__ A_log,
                            const float* __restrict__ dt_bias) {
    int i = blockIdx.x*blockDim.x + threadIdx.x;
    if (i >= LSEQ*NH) return;
    int h = i & 7;
    float xg = a[i] + dt_bias[h];
    float sp = (xg > 20.f) ? xg : log1pf(expf(xg));
    g_gb[i] = make_float2(-expf(A_log[h]) * sp, 1.f/(1.f + expf(-b[i])));
}

// ---------------------------------------------------------------------------
// K3: chunk-local inclusive cumsum + exponentials. grid CHH, block 32.
// ---------------------------------------------------------------------------
__global__ void cumsum_kernel() {
    int ch = blockIdx.x, n = ch >> 3, h = ch & 7, t = threadIdx.x;
    float2 gb = g_gb[(n*CH + t)*NH + h];
    float s = gb.x;
    #pragma unroll
    for (int off = 1; off < 32; off <<= 1) {
        float o = __shfl_up_sync(0xffffffffu, s, off);
        if (t >= off) s += o;
    }
    float cg31 = __shfl_sync(0xffffffffu, s, 31);
    g_sc[ch*CH + t] = make_float4(__expf(s), gb.y, __expf(cg31 - s), s);
    if (t == 31) g_gamma[ch] = __expf(s);
}

// ---------------------------------------------------------------------------
// K4: Gram matrices A, M.  grid CHH, block 256.
// ---------------------------------------------------------------------------
__global__ void __launch_bounds__(256) gram_kernel() {
    __shared__ float Kg[CH][132], Qg[CH][132];
    __shared__ float cg[CH], bet[CH];
    const int ch = blockIdx.x, n = ch >> 3, h = ch & 7, tid = threadIdx.x;

    for (int i = tid; i < CH*32; i += 256) {
        int r = i >> 5, c4 = i & 31;
        cp16(&Kg[r][c4*4], g_k + ((n*CH + r)*NH + h)*DKH + c4*4);
        cp16(&Qg[r][c4*4], g_q + ((n*CH + r)*NH + h)*DKH + c4*4);
    }
    cp_commit();
    if (tid < CH) {
        float4 s = g_sc[ch*CH + tid];
        cg[tid] = s.w; bet[tid] = s.y;
    }
    cp_wait<0>(); __syncthreads();

    const int ti = (tid >> 4) * 2, tj = (tid & 15) * 2;
    float a00=0,a01=0,a10=0,a11=0, m00=0,m01=0,m10=0,m11=0;
    #pragma unroll 4
    for (int c4 = 0; c4 < 32; c4++) {
        float4 k0 = *(float4*)&Kg[ti  ][c4*4];
        float4 k1 = *(float4*)&Kg[ti+1][c4*4];
        float4 j0 = *(float4*)&Kg[tj  ][c4*4];
        float4 j1 = *(float4*)&Kg[tj+1][c4*4];
        float4 q0 = *(float4*)&Qg[ti  ][c4*4];
        float4 q1 = *(float4*)&Qg[ti+1][c4*4];
        a00 = fmaf(k0.x,j0.x,fmaf(k0.y,j0.y,fmaf(k0.z,j0.z,fmaf(k0.w,j0.w,a00))));
        a01 = fmaf(k0.x,j1.x,fmaf(k0.y,j1.y,fmaf(k0.z,j1.z,fmaf(k0.w,j1.w,a01))));
        a10 = fmaf(k1.x,j0.x,fmaf(k1.y,j0.y,fmaf(k1.z,j0.z,fmaf(k1.w,j0.w,a10))));
        a11 = fmaf(k1.x,j1.x,fmaf(k1.y,j1.y,fmaf(k1.z,j1.z,fmaf(k1.w,j1.w,a11))));
        m00 = fmaf(q0.x,j0.x,fmaf(q0.y,j0.y,fmaf(q0.z,j0.z,fmaf(q0.w,j0.w,m00))));
        m01 = fmaf(q0.x,j1.x,fmaf(q0.y,j1.y,fmaf(q0.z,j1.z,fmaf(q0.w,j1.w,m01))));
        m10 = fmaf(q1.x,j0.x,fmaf(q1.y,j0.y,fmaf(q1.z,j0.z,fmaf(q1.w,j0.w,m10))));
        m11 = fmaf(q1.x,j1.x,fmaf(q1.y,j1.y,fmaf(q1.z,j1.z,fmaf(q1.w,j1.w,m11))));
    }
    float av[4] = {a00,a01,a10,a11}, mv[4] = {m00,m01,m10,m11};
    #pragma unroll
    for (int di = 0; di < 2; di++)
        #pragma unroll
        for (int dj = 0; dj < 2; dj++) {
            int t = ti + di, j = tj + dj;
            float e = __expf(cg[t] - cg[j]);
            g_A[ch*(CH*CH) + t*CH + j] = (j < t)  ? bet[t]*e*av[di*2+dj] : 0.f;
            g_M[ch*(CH*36) + t*36 + j] = (j <= t) ? e*mv[di*2+dj]        : 0.f;
        }
}

// ---------------------------------------------------------------------------
// K5: T = (I+A)^-1 forward substitution, column-parallel. grid CHH, blk 32.
// ---------------------------------------------------------------------------
__global__ void tinv_kernel() {
    __shared__ float A[CH][CH], T[CH][36];
    const int ch = blockIdx.x, c = threadIdx.x;
    for (int i = 0; i < CH; i++) A[i][c] = g_A[ch*(CH*CH) + i*CH + c];
    __syncwarp();
    for (int t = 0; t < CH; t++) {
        float acc = 0.f;
        for (int j = 0; j < t; j++) acc = fmaf(A[t][j], T[j][c], acc);
        T[t][c] = ((t == c) ? 1.f : 0.f) - acc;
        __syncwarp();
    }
    for (int i = 0; i < CH; i++) g_T[ch*(CH*36) + i*36 + c] = T[i][c];
}

// ---------------------------------------------------------------------------
// K6: sequential chunk scan + fused output. grid 128 (h,vb), block 512.
// Role split: threads 0-255 ("d-group") compute K.S0 -> b -> u = T.b;
// threads 256-511 ("q-group") compute Q.S0 and later M.u + output store,
// overlapping the all-thread rank-32 state update. State float2/thread.
// ---------------------------------------------------------------------------
// dynamic smem layout (floats):
#define OK   0                        // sK [2][32][132]
#define OQ   (OK + 2*32*132)          // sQ [2][32][132]
#define OT_  (OQ + 2*32*132)          // sT [2][32][36]
#define OM_  (OT_ + 2*32*36)          // sM [2][32][36]
#define OST  (OM_ + 2*32*36)          // sST [8][132]  (cc-major state mirror)
#define OBT  (OST + 8*132)            // sBt [8][36]   (b transposed)
#define OU_  (OBT + 8*36)             // sU  [32][8]   (u * z)
#define OUT_ (OU_ + 32*8)             // sUt [8][36]   (u raw, transposed)
#define SEQ_SMEM_FLOATS (OUT_ + 8*36)
#define SEQ_SMEM_BYTES (SEQ_SMEM_FLOATS*4)

__device__ __forceinline__ void load_tiles(float* dsm, int n, int b, int h, int tid) {
    for (int i = tid; i < CH*32; i += 512) {
        int r = i >> 5, c4 = i & 31;
        cp16(&dsm[OK + b*4224 + r*132 + c4*4], g_k + ((n*CH + r)*NH + h)*DKH + c4*4);
        cp16(&dsm[OQ + b*4224 + r*132 + c4*4], g_q + ((n*CH + r)*NH + h)*DKH + c4*4);
    }
    int ch = n*NH + h;
    if (tid < 288) {
        int r = tid/9, c4 = tid - r*9;    // 9 float4 per 36-float row
        cp16(&dsm[OT_ + b*1152 + r*36 + c4*4], g_T + ch*(CH*36) + r*36 + c4*4);
        cp16(&dsm[OM_ + b*1152 + r*36 + c4*4], g_M + ch*(CH*36) + r*36 + c4*4);
    }
}

__global__ void __launch_bounds__(512) seq_kernel(float* __restrict__ out) {
    extern __shared__ float dsm[];
    const int tid = threadIdx.x;
    const int h  = blockIdx.x >> 4;
    const int vb = blockIdx.x & 15;
    const int tt = (tid & 255) >> 3, cc = tid & 7;  // (t, col) for both groups
    const bool dgrp = tid < 256;
    const int kk = tid & 127, c2 = (tid >> 7) * 2;  // state: k-dim kk, cols c2,c2+1
    // NOTE: c2 uses tid>>7 in 0..3 -> wait, tid>>7 in 0..3 gives c2 in {0,2,4,6}
    // combined with 128 kk values -> 4 col-pairs * 128 kk = 512 slots exactly.

    for (int i = tid; i < 8*132; i += 512) dsm[OST + i] = 0.f;

    load_tiles(dsm, 0, 0, h, tid);
    cp_commit();

    float2 s2 = make_float2(0.f, 0.f);              // register state (2 cols)
    float  vcur  = dgrp ? g_v[(tt*NH + h)*DVH + vb*8 + cc] : 0.f;
    float4 sccur = g_sc[h*CH + tt];
    float  gcur  = g_gamma[h];
    cp_wait<0>(); __syncthreads();

    for (int n = 0; n < NCH; n++) {
        const int cb = n & 1;
        if (n + 1 < NCH) { load_tiles(dsm, n+1, cb^1, h, tid); cp_commit(); }

        // ---- step1: d-group: K.S0 ; q-group: Q.S0 ----
        const float* mat = dgrp ? &dsm[OK + cb*4224 + tt*132]
                                : &dsm[OQ + cb*4224 + tt*132];
        float a0=0,a1=0,a2=0,a3=0;
        #pragma unroll
        for (int c4 = 0; c4 < 32; c4++) {
            float4 s = *(float4*)&dsm[OST + cc*132 + c4*4];
            float4 m = *(float4*)&mat[c4*4];
            a0 = fmaf(m.x, s.x, a0); a1 = fmaf(m.y, s.y, a1);
            a2 = fmaf(m.z, s.z, a2); a3 = fmaf(m.w, s.w, a3);
        }
        float sum = (a0+a1) + (a2+a3);
        float o1v = 0.f;
        if (dgrp) dsm[OBT + cc*36 + tt] = sccur.y * (vcur - sccur.x * sum);
        else      o1v = sccur.x * sum;

        // prefetch next-chunk scalars (off critical path)
        float vnext = 0.f, gnext = 0.f; float4 scnext = make_float4(0,0,0,0);
        if (n + 1 < NCH) {
            if (dgrp) vnext = g_v[(((n+1)*CH + tt)*NH + h)*DVH + vb*8 + cc];
            scnext = g_sc[((n+1)*NH + h)*CH + tt];
            gnext  = g_gamma[(n+1)*NH + h];
        }
        __syncthreads();

        // ---- step3: u = T.b (d-group only) ----
        if (dgrp) {
            float u0=0,u1=0,u2=0,u3=0;
            #pragma unroll
            for (int j4 = 0; j4 < 8; j4++) {
                float4 tv = *(float4*)&dsm[OT_ + cb*1152 + tt*36 + j4*4];
                float4 bv = *(float4*)&dsm[OBT + cc*36 + j4*4];
                u0 = fmaf(tv.x, bv.x, u0); u1 = fmaf(tv.y, bv.y, u1);
                u2 = fmaf(tv.z, bv.z, u2); u3 = fmaf(tv.w, bv.w, u3);
            }
            float u = (u0+u1) + (u2+u3);
            dsm[OU_ + tt*8 + cc]   = u * sccur.z;   // scaled for state update
            dsm[OUT_ + cc*36 + tt] = u;             // raw for M.u
        }
        __syncthreads();

        // ---- q-group: o = E*(Q.S0) + M.u  (overlaps step4 below) ----
        if (!dgrp) {
            float m0=0,m1=0,m2=0,m3=0;
            #pragma unroll
            for (int j4 = 0; j4 < 8; j4++) {
                float4 mv = *(float4*)&dsm[OM_ + cb*1152 + tt*36 + j4*4];
                float4 uv = *(float4*)&dsm[OUT_ + cc*36 + j4*4];
                m0 = fmaf(mv.x, uv.x, m0); m1 = fmaf(mv.y, uv.y, m1);
                m2 = fmaf(mv.z, uv.z, m2); m3 = fmaf(mv.w, uv.w, m3);
            }
            out[(n*CH + tt)*(NH*DVH) + h*DVH + vb*8 + cc]
                = o1v + ((m0+m1) + (m2+m3));
        }

        // ---- step4: S = gam*S + K^T.(u*z)  (all threads, float2 state) ----
        s2.x *= gcur; s2.y *= gcur;
        #pragma unroll
        for (int t2 = 0; t2 < CH; t2++) {
            float  kv = dsm[OK + cb*4224 + t2*132 + kk];
            float2 uu = *(float2*)&dsm[OU_ + t2*8 + c2];
            s2.x = fmaf(kv, uu.x, s2.x);
            s2.y = fmaf(kv, uu.y, s2.y);
        }
        dsm[OST + (c2+0)*132 + kk] = s2.x;
        dsm[OST + (c2+1)*132 + kk] = s2.y;

        cp_wait<0>(); __syncthreads();
        vcur = vnext; sccur = scnext; gcur = gnext;
    }
}

// ---------------------------------------------------------------------------
extern "C" void kernel_launch(void* const* d_in, const int* in_sizes, int n_in,
                              void* d_out, int out_size) {
    const float* x       = (const float*)d_in[0];
    const float* a       = (const float*)d_in[1];
    const float* bgate   = (const float*)d_in[2];
    const float* A_log   = (const float*)d_in[3];
    const float* dt_bias = (const float*)d_in[4];
    const float* w       = (const float*)d_in[5];
    const float* bias    = (const float*)d_in[6];
    float* out = (float*)d_out;

    static int attr_set = 0;
    if (!attr_set) {
        cudaFuncSetAttribute(seq_kernel,
            cudaFuncAttributeMaxDynamicSharedMemorySize, SEQ_SMEM_BYTES);
        attr_set = 1;
    }

    prep_kernel<<<dim3(LSEQ/4, 24), 128>>>(x, w, bias);
    gate_kernel<<<(LSEQ*NH + 255)/256, 256>>>(a, bgate, A_log, dt_bias);
    cumsum_kernel<<<CHH, 32>>>();
    gram_kernel<<<CHH, 256>>>();
    tinv_kernel<<<CHH, 32>>>();
    seq_kernel<<<128, 512, SEQ_SMEM_BYTES>>>(out);
}

// round 10
// speedup vs baseline: 1.2861x; 1.2861x over previous
#include <cuda_runtime.h>

#define LSEQ 2048
#define NH 8
#define DKH 128
#define DVH 128
#define CIN 3072
#define CH 32
#define NCH (LSEQ/CH)        // 64
#define CHH (NCH*NH)         // 512 chunk-heads

typedef unsigned long long ull;

// ------------------------- global scratch (static) -------------------------
__device__ float  g_q [LSEQ*NH*DKH];
__device__ float  g_k [LSEQ*NH*DKH];
__device__ float  g_v [LSEQ*NH*DVH];
__device__ float4 g_sc[CHH*CH];           // (E_t, beta_t, exp(cg31-cg_t), cg_t)
__device__ float  g_gamma[CHH];           // E_31 per chunk-head
__device__ float  g_M[CHH*CH*36];         // lower-incl M (padded rows, 36; pads stay 0)
__device__ float  g_T[CHH*CH*36];         // (I+A)^-1   (padded rows, 36; pads stored 0)

// ------------------------- helpers -------------------------
__device__ __forceinline__ unsigned smem_u32(const void* p) {
    return (unsigned)__cvta_generic_to_shared(p);
}
__device__ __forceinline__ void cp16(void* dst, const void* src) {
    asm volatile("cp.async.cg.shared.global [%0], [%1], 16;" :: "r"(smem_u32(dst)), "l"(src));
}
__device__ __forceinline__ void cp_commit() { asm volatile("cp.async.commit_group;"); }
template<int N> __device__ __forceinline__ void cp_wait() {
    asm volatile("cp.async.wait_group %0;" :: "n"(N));
}
// packed fp32 pair ops (Blackwell f32x2) — register-pure asm, safe non-volatile
__device__ __forceinline__ ull ffma2(ull a, ull b, ull c) {
    ull d; asm("fma.rn.f32x2 %0, %1, %2, %3;" : "=l"(d) : "l"(a), "l"(b), "l"(c));
    return d;
}
__device__ __forceinline__ ull fmul2(ull a, ull b) {
    ull d; asm("mul.rn.f32x2 %0, %1, %2;" : "=l"(d) : "l"(a), "l"(b));
    return d;
}
__device__ __forceinline__ ull pack2(float x, float y) {
    ull r; asm("mov.b64 %0, {%1, %2};" : "=l"(r) : "f"(x), "f"(y)); return r;
}
__device__ __forceinline__ void unpack2(ull v, float& x, float& y) {
    asm("mov.b64 {%0, %1}, %2;" : "=f"(x), "=f"(y) : "l"(v));
}
__device__ __forceinline__ float hsum2(ull v) {
    float x, y; unpack2(v, x, y); return x + y;
}
// 16B shared load as two packed f32 pairs — plain C++ load (LDS.128) so the
// compiler keeps correct ordering vs. barriers / cp.async waits / smem stores.
__device__ __forceinline__ void lds2(ull& a, ull& b, const float* p) {
    ulonglong2 v = *(const ulonglong2*)p;
    a = v.x; b = v.y;
}

// ---------------------------------------------------------------------------
// K1: conv(K=4)+SiLU+split+l2norm. 4 timesteps per block. grid (512,24), blk 128.
// ---------------------------------------------------------------------------
__global__ void prep_kernel(const float* __restrict__ x,
                            const float* __restrict__ w,
                            const float* __restrict__ bias) {
    const int t0 = blockIdx.x * 4;
    const int g = blockIdx.y, d = threadIdx.x;
    const int c = g*128 + d;
    const float4 wv = ((const float4*)w)[c];
    const float bi = bias[c];

    float xw[7];
    #pragma unroll
    for (int i = 0; i < 7; i++) {
        int t = t0 - 3 + i;
        xw[i] = (t >= 0) ? x[t*CIN + c] : 0.f;
    }
    float val[4];
    #pragma unroll
    for (int i = 0; i < 4; i++) {
        float acc = bi;
        acc = fmaf(xw[i  ], wv.x, acc);
        acc = fmaf(xw[i+1], wv.y, acc);
        acc = fmaf(xw[i+2], wv.z, acc);
        acc = fmaf(xw[i+3], wv.w, acc);
        val[i] = acc / (1.f + __expf(-acc));
    }

    __shared__ float red[4][4];
    if (g < 16) {
        float sq[4];
        #pragma unroll
        for (int i = 0; i < 4; i++) sq[i] = val[i]*val[i];
        #pragma unroll
        for (int off = 16; off; off >>= 1) {
            #pragma unroll
            for (int i = 0; i < 4; i++) sq[i] += __shfl_xor_sync(0xffffffffu, sq[i], off);
        }
        if ((d & 31) == 0) {
            #pragma unroll
            for (int i = 0; i < 4; i++) red[i][d >> 5] = sq[i];
        }
        __syncthreads();
        #pragma unroll
        for (int i = 0; i < 4; i++)
            val[i] *= rsqrtf(red[i][0]+red[i][1]+red[i][2]+red[i][3] + 1e-6f);
    }
    #pragma unroll
    for (int i = 0; i < 4; i++) {
        int t = t0 + i;
        if (g < 8)       g_q[(t*NH + g)*DKH + d]      = val[i] * 0.08838834764831845f;
        else if (g < 16) g_k[(t*NH + (g-8))*DKH + d]  = val[i];
        else             g_v[(t*NH + (g-16))*DVH + d] = val[i];
    }
}

// ---------------------------------------------------------------------------
// K2: gating + chunk-local cumsum + exponentials. grid CHH, block 32.
// ---------------------------------------------------------------------------
__global__ void gatecum_kernel(const float* __restrict__ a,
                               const float* __restrict__ b,
                               const float* __restrict__ A_log,
                               const float* __restrict__ dt_bias) {
    int ch = blockIdx.x, n = ch >> 3, h = ch & 7, t = threadIdx.x;
    int i = (n*CH + t)*NH + h;
    float xg = a[i] + dt_bias[h];
    float sp = (xg > 20.f) ? xg : log1pf(expf(xg));
    float gg = -expf(A_log[h]) * sp;
    float bt = 1.f/(1.f + expf(-b[i]));
    float s = gg;
    #pragma unroll
    for (int off = 1; off < 32; off <<= 1) {
        float o = __shfl_up_sync(0xffffffffu, s, off);
        if (t >= off) s += o;
    }
    float cg31 = __shfl_sync(0xffffffffu, s, 31);
    g_sc[ch*CH + t] = make_float4(__expf(s), bt, __expf(cg31 - s), s);
    if (t == 31) g_gamma[ch] = __expf(s);
}

// ---------------------------------------------------------------------------
// K3: Gram matrices A, M + T = (I+A)^-1, fused. grid CHH, block 256.
// ---------------------------------------------------------------------------
__global__ void __launch_bounds__(256) gramtinv_kernel() {
    __shared__ float Kg[CH][132], Qg[CH][132];
    __shared__ float sA[CH][33], sT[CH][36];
    __shared__ float cg[CH], bet[CH];
    const int ch = blockIdx.x, n = ch >> 3, h = ch & 7, tid = threadIdx.x;

    for (int i = tid; i < CH*32; i += 256) {
        int r = i >> 5, c4 = i & 31;
        cp16(&Kg[r][c4*4], g_k + ((n*CH + r)*NH + h)*DKH + c4*4);
        cp16(&Qg[r][c4*4], g_q + ((n*CH + r)*NH + h)*DKH + c4*4);
    }
    cp_commit();
    if (tid < CH) {
        float4 s = g_sc[ch*CH + tid];
        cg[tid] = s.w; bet[tid] = s.y;
    }
    cp_wait<0>(); __syncthreads();

    const int ti = (tid >> 4) * 2, tj = (tid & 15) * 2;
    ull pa[2][2][2], pm[2][2][2];   // [di][dj][pairhalf] packed accumulators
    #pragma unroll
    for (int di = 0; di < 2; di++)
        #pragma unroll
        for (int dj = 0; dj < 2; dj++) {
            pa[di][dj][0]=0; pa[di][dj][1]=0; pm[di][dj][0]=0; pm[di][dj][1]=0;
        }
    #pragma unroll 4
    for (int c4 = 0; c4 < 32; c4++) {
        ull k0a,k0b,k1a,k1b, j0a,j0b,j1a,j1b, q0a,q0b,q1a,q1b;
        lds2(k0a,k0b,&Kg[ti  ][c4*4]);
        lds2(k1a,k1b,&Kg[ti+1][c4*4]);
        lds2(j0a,j0b,&Kg[tj  ][c4*4]);
        lds2(j1a,j1b,&Kg[tj+1][c4*4]);
        lds2(q0a,q0b,&Qg[ti  ][c4*4]);
        lds2(q1a,q1b,&Qg[ti+1][c4*4]);
        pa[0][0][0]=ffma2(k0a,j0a,pa[0][0][0]); pa[0][0][1]=ffma2(k0b,j0b,pa[0][0][1]);
        pa[0][1][0]=ffma2(k0a,j1a,pa[0][1][0]); pa[0][1][1]=ffma2(k0b,j1b,pa[0][1][1]);
        pa[1][0][0]=ffma2(k1a,j0a,pa[1][0][0]); pa[1][0][1]=ffma2(k1b,j0b,pa[1][0][1]);
        pa[1][1][0]=ffma2(k1a,j1a,pa[1][1][0]); pa[1][1][1]=ffma2(k1b,j1b,pa[1][1][1]);
        pm[0][0][0]=ffma2(q0a,j0a,pm[0][0][0]); pm[0][0][1]=ffma2(q0b,j0b,pm[0][0][1]);
        pm[0][1][0]=ffma2(q0a,j1a,pm[0][1][0]); pm[0][1][1]=ffma2(q0b,j1b,pm[0][1][1]);
        pm[1][0][0]=ffma2(q1a,j0a,pm[1][0][0]); pm[1][0][1]=ffma2(q1b,j0b,pm[1][0][1]);
        pm[1][1][0]=ffma2(q1a,j1a,pm[1][1][0]); pm[1][1][1]=ffma2(q1b,j1b,pm[1][1][1]);
    }
    #pragma unroll
    for (int di = 0; di < 2; di++)
        #pragma unroll
        for (int dj = 0; dj < 2; dj++) {
            int t = ti + di, j = tj + dj;
            float e = __expf(cg[t] - cg[j]);
            float av = hsum2(pa[di][dj][0]) + hsum2(pa[di][dj][1]);
            float mv = hsum2(pm[di][dj][0]) + hsum2(pm[di][dj][1]);
            sA[t][j] = (j < t)  ? bet[t]*e*av : 0.f;
            g_M[ch*(CH*36) + t*36 + j] = (j <= t) ? e*mv : 0.f;
        }
    __syncthreads();

    // forward substitution: T = (I+A)^-1, rank-1-update form, warp 0
    if (tid < 32) {
        const int c = tid;
        float acc[CH];
        #pragma unroll
        for (int r = 0; r < CH; r++) acc[r] = 0.f;
        #pragma unroll
        for (int t = 0; t < CH; t++) {
            float Ttc = ((t == c) ? 1.f : 0.f) - acc[t];
            sT[t][c] = Ttc;
            #pragma unroll
            for (int r = t+1; r < CH; r++)
                acc[r] = fmaf(sA[r][t], Ttc, acc[r]);
        }
    }
    __syncthreads();
    // store T; pad columns (32..35) written as 0, never smem garbage
    for (int i = tid; i < CH*36; i += 256) {
        int col = i % 36;
        g_T[ch*(CH*36) + i] = (col < 32) ? (&sT[0][0])[i] : 0.f;
    }
}

// ---------------------------------------------------------------------------
// K4: sequential chunk scan + fused output. grid 128 (h,vb), block 256.
// ---------------------------------------------------------------------------
#define OK   0                        // sK [2][32][132]
#define OQ   (OK + 2*32*132)          // sQ [2][32][132]
#define OT_  (OQ + 2*32*132)          // sT [2][32][36]
#define OM_  (OT_ + 2*32*36)          // sM [2][32][36]
#define OST  (OM_ + 2*32*36)          // sST [8][132]  (cc-major state mirror)
#define OBT  (OST + 8*132)            // sBt [8][36]   (b transposed)
#define OU_  (OBT + 8*36)             // sU  [32][8]   (u * z)
#define OUT_ (OU_ + 32*8)             // sUt [8][36]   (u raw, transposed)
#define SEQ_SMEM_FLOATS (OUT_ + 8*36)
#define SEQ_SMEM_BYTES (SEQ_SMEM_FLOATS*4)

__device__ __forceinline__ void load_tiles(float* dsm, int n, int b, int h, int tid) {
    for (int i = tid; i < CH*32; i += 256) {
        int r = i >> 5, c4 = i & 31;
        cp16(&dsm[OK + b*4224 + r*132 + c4*4], g_k + ((n*CH + r)*NH + h)*DKH + c4*4);
        cp16(&dsm[OQ + b*4224 + r*132 + c4*4], g_q + ((n*CH + r)*NH + h)*DKH + c4*4);
    }
    int ch = n*NH + h;
    for (int i = tid; i < 288; i += 256) {
        int r = i/9, c4 = i - r*9;
        cp16(&dsm[OT_ + b*1152 + r*36 + c4*4], g_T + ch*(CH*36) + r*36 + c4*4);
        cp16(&dsm[OM_ + b*1152 + r*36 + c4*4], g_M + ch*(CH*36) + r*36 + c4*4);
    }
}

__global__ void __launch_bounds__(256) seq_kernel(float* __restrict__ out) {
    extern __shared__ float dsm[];
    const int tid = threadIdx.x;
    const int h  = blockIdx.x >> 4;
    const int vb = blockIdx.x & 15;
    const int tt = tid >> 3, cc = tid & 7;          // (t, col) identity
    const int kk = tid & 127, cg4 = (tid >> 7)*4;   // (kdim, col4) identity

    for (int i = tid; i < 8*132; i += 256) dsm[OST + i] = 0.f;
    for (int i = tid; i < 8*36; i += 256) { dsm[OBT + i] = 0.f; dsm[OUT_ + i] = 0.f; }

    load_tiles(dsm, 0, 0, h, tid);
    cp_commit();

    ull s01 = 0, s23 = 0;                           // register state (4 cols, packed)
    float  vcur  = g_v[(tt*NH + h)*DVH + vb*8 + cc];
    float4 sccur = g_sc[h*CH + tt];
    float  gcur  = g_gamma[h];
    cp_wait<0>(); __syncthreads();

    for (int n = 0; n < NCH; n++) {
        const int cb = n & 1;
        if (n + 1 < NCH) { load_tiles(dsm, n+1, cb^1, h, tid); cp_commit(); }

        // ---- step1: d = K.S0, qs = Q.S0 (shared s loads, packed fma) ----
        ull d01=0,d23=0, e01=0,e23=0;
        #pragma unroll
        for (int c4 = 0; c4 < 32; c4++) {
            ull sa,sb, ka,kb, qa,qb;
            lds2(sa,sb,&dsm[OST + cc*132 + c4*4]);
            lds2(ka,kb,&dsm[OK + cb*4224 + tt*132 + c4*4]);
            lds2(qa,qb,&dsm[OQ + cb*4224 + tt*132 + c4*4]);
            d01 = ffma2(ka,sa,d01); d23 = ffma2(kb,sb,d23);
            e01 = ffma2(qa,sa,e01); e23 = ffma2(qb,sb,e23);
        }
        float dd  = hsum2(d01) + hsum2(d23);
        float o1v = sccur.x * (hsum2(e01) + hsum2(e23));
        dsm[OBT + cc*36 + tt] = sccur.y * (vcur - sccur.x * dd);

        // prefetch next-chunk scalars (off critical path)
        float vnext = 0.f, gnext = 0.f; float4 scnext = make_float4(0,0,0,0);
        if (n + 1 < NCH) {
            vnext  = g_v[(((n+1)*CH + tt)*NH + h)*DVH + vb*8 + cc];
            scnext = g_sc[((n+1)*NH + h)*CH + tt];
            gnext  = g_gamma[(n+1)*NH + h];
        }
        __syncthreads();

        // ---- step3: u = T.b ----
        ull u01=0,u23=0;
        #pragma unroll
        for (int j4 = 0; j4 < 8; j4++) {
            ull ta,tb, ba,bb;
            lds2(ta,tb,&dsm[OT_ + cb*1152 + tt*36 + j4*4]);
            lds2(ba,bb,&dsm[OBT + cc*36 + j4*4]);
            u01 = ffma2(ta,ba,u01); u23 = ffma2(tb,bb,u23);
        }
        float u = hsum2(u01) + hsum2(u23);
        dsm[OU_ + tt*8 + cc]   = u * sccur.z;   // scaled for state update
        dsm[OUT_ + cc*36 + tt] = u;             // raw for M.u
        __syncthreads();

        // ---- output: o = E*(Q.S0) + M.u ----
        ull m01=0,m23=0;
        #pragma unroll
        for (int j4 = 0; j4 < 8; j4++) {
            ull ma,mb, ua,ub;
            lds2(ma,mb,&dsm[OM_ + cb*1152 + tt*36 + j4*4]);
            lds2(ua,ub,&dsm[OUT_ + cc*36 + j4*4]);
            m01 = ffma2(ma,ua,m01); m23 = ffma2(mb,ub,m23);
        }
        out[(n*CH + tt)*(NH*DVH) + h*DVH + vb*8 + cc]
            = o1v + hsum2(m01) + hsum2(m23);

        // ---- step4: S = gam*S + K^T.(u*z)  (register state, packed) ----
        {
            ull gg = pack2(gcur, gcur);
            s01 = fmul2(s01, gg); s23 = fmul2(s23, gg);
            #pragma unroll
            for (int t2 = 0; t2 < CH; t2++) {
                float kv = dsm[OK + cb*4224 + t2*132 + kk];
                ull kvv = pack2(kv, kv);
                ull ua, ub;
                lds2(ua, ub, &dsm[OU_ + t2*8 + cg4]);
                s01 = ffma2(kvv, ua, s01);
                s23 = ffma2(kvv, ub, s23);
            }
            float f0,f1,f2,f3;
            unpack2(s01, f0, f1); unpack2(s23, f2, f3);
            dsm[OST + (cg4+0)*132 + kk] = f0;
            dsm[OST + (cg4+1)*132 + kk] = f1;
            dsm[OST + (cg4+2)*132 + kk] = f2;
            dsm[OST + (cg4+3)*132 + kk] = f3;
        }

        cp_wait<0>(); __syncthreads();
        vcur = vnext; sccur = scnext; gcur = gnext;
    }
}

// ---------------------------------------------------------------------------
extern "C" void kernel_launch(void* const* d_in, const int* in_sizes, int n_in,
                              void* d_out, int out_size) {
    const float* x       = (const float*)d_in[0];
    const float* a       = (const float*)d_in[1];
    const float* bgate   = (const float*)d_in[2];
    const float* A_log   = (const float*)d_in[3];
    const float* dt_bias = (const float*)d_in[4];
    const float* w       = (const float*)d_in[5];
    const float* bias    = (const float*)d_in[6];
    float* out = (float*)d_out;

    static int attr_set = 0;
    if (!attr_set) {
        cudaFuncSetAttribute(seq_kernel,
            cudaFuncAttributeMaxDynamicSharedMemorySize, SEQ_SMEM_BYTES);
        attr_set = 1;
    }

    prep_kernel<<<dim3(LSEQ/4, 24), 128>>>(x, w, bias);
    gatecum_kernel<<<CHH, 32>>>(a, bgate, A_log, dt_bias);
    gramtinv_kernel<<<CHH, 256>>>();
    seq_kernel<<<128, 256, SEQ_SMEM_BYTES>>>(out);
}